// round 3
// baseline (speedup 1.0000x reference)
#include <cuda_runtime.h>

// ---------------------------------------------------------------------------
// GCN_13898514169996: 2-layer GCN, N=100000 nodes, E=3.2M edges, 512->16->7.
// out = log_softmax( gcn2( relu( gcn1(X) ) ) )
// gcn(h)[v] = dinv[v] * ( sum_{u->v} h[u]*dinv[u]  +  h[v]*dinv[v] ) + b
// where deg[v] = 1 + indegree(v), dinv = rsqrt(deg).
//
// NOTE: edge_index arrives as int32 (JAX x64 disabled downcasts the reference's
// int64 request). Reading it as int64 was the round-1/2 err-717 trap.
// ---------------------------------------------------------------------------

#define MAXN 100000

__device__ float g_hs  [MAXN * 16];  // (X@W1) * dinv[row]
__device__ float g_acc1[MAXN * 16];  // edge-scattered sums, layer 1
__device__ float g_hs2 [MAXN * 8];   // (h1@W2) * dinv[row], padded to 8
__device__ float g_acc2[MAXN * 8];   // edge-scattered sums, layer 2
__device__ int   g_deg [MAXN];
__device__ float g_dinv[MAXN];

// ---- init: deg=1 (self loop), zero accumulators -----------------------------
__global__ void k_init(int n) {
    int v = blockIdx.x * blockDim.x + threadIdx.x;
    if (v >= n) return;
    g_deg[v] = 1;
    float4 z = make_float4(0.f, 0.f, 0.f, 0.f);
    float4* a1 = (float4*)(g_acc1 + (size_t)v * 16);
    a1[0] = z; a1[1] = z; a1[2] = z; a1[3] = z;
    float4* a2 = (float4*)(g_acc2 + (size_t)v * 8);
    a2[0] = z; a2[1] = z;
}

// ---- in-degree count ---------------------------------------------------------
__global__ void k_deg(const int* __restrict__ dst, int E) {
    int i = blockIdx.x * blockDim.x + threadIdx.x;
    if (i >= E) return;
    atomicAdd(&g_deg[dst[i]], 1);   // value unused -> RED
}

__global__ void k_dinv(int n) {
    int v = blockIdx.x * blockDim.x + threadIdx.x;
    if (v >= n) return;
    g_dinv[v] = rsqrtf((float)g_deg[v]);
}

// ---- GEMM1: hs = (X @ W1) * dinv[row].  X:[n,512], W1:[512,16] ---------------
// Block: 256 threads = 32 rows x 8 col-pairs; each thread computes 2 outputs.
__global__ void __launch_bounds__(256) k_gemm1(const float* __restrict__ x,
                                               const float* __restrict__ W1,
                                               int n) {
    __shared__ float Ws[512 * 16];
    int t = threadIdx.x;
    #pragma unroll
    for (int i = t; i < 8192; i += 256) Ws[i] = W1[i];
    __syncthreads();

    int r  = t >> 3;   // 0..31 : row within tile
    int jc = t & 7;    // 0..7  : column pair (j = 2*jc, 2*jc+1)
    int row = blockIdx.x * 32 + r;
    if (row >= n) return;

    const float4* xr = (const float4*)(x + (size_t)row * 512);
    const float2* wp = (const float2*)Ws;   // [k][8] float2
    float ax = 0.f, ay = 0.f;
    #pragma unroll 8
    for (int k4 = 0; k4 < 128; k4++) {
        float4 xv = __ldg(xr + k4);
        float2 w0 = wp[(k4 * 4 + 0) * 8 + jc];
        float2 w1 = wp[(k4 * 4 + 1) * 8 + jc];
        float2 w2 = wp[(k4 * 4 + 2) * 8 + jc];
        float2 w3 = wp[(k4 * 4 + 3) * 8 + jc];
        ax += xv.x * w0.x;  ay += xv.x * w0.y;
        ax += xv.y * w1.x;  ay += xv.y * w1.y;
        ax += xv.z * w2.x;  ay += xv.z * w2.y;
        ax += xv.w * w3.x;  ay += xv.w * w3.y;
    }
    float dv = g_dinv[row];
    g_hs[(size_t)row * 16 + 2 * jc]     = ax * dv;
    g_hs[(size_t)row * 16 + 2 * jc + 1] = ay * dv;
}

// ---- edge scatter, layer 1: acc1[dst] += hs[src], 4 threads per edge --------
// Each thread handles one float4 quarter: 1x 16B ldg + 4 scalar REDs.
__global__ void k_scatter1(const int* __restrict__ src,
                           const int* __restrict__ dst, int E) {
    int i = blockIdx.x * blockDim.x + threadIdx.x;
    int e = i >> 2;
    if (e >= E) return;
    int q = i & 3;
    size_t s = (size_t)src[e];
    size_t d = (size_t)dst[e];
    float4 a = __ldg((const float4*)(g_hs + s * 16) + q);
    float* o = g_acc1 + d * 16 + q * 4;
    atomicAdd(o + 0, a.x);
    atomicAdd(o + 1, a.y);
    atomicAdd(o + 2, a.z);
    atomicAdd(o + 3, a.w);
}

// ---- layer-1 epilogue + layer-2 node GEMM ------------------------------------
// h1 = relu( dinv*(acc1+hs) + b1 );  hs2 = (h1 @ W2) * dinv  (padded to 8)
__global__ void __launch_bounds__(256) k_layer2(const float* __restrict__ b1,
                                                const float* __restrict__ W2,
                                                int n) {
    __shared__ float W2s[112];
    __shared__ float b1s[16];
    int t = threadIdx.x;
    if (t < 112) W2s[t] = W2[t];
    if (t < 16)  b1s[t] = b1[t];
    __syncthreads();

    int v = blockIdx.x * 256 + t;
    if (v >= n) return;
    float dv = g_dinv[v];
    const float4* ap = (const float4*)(g_acc1 + (size_t)v * 16);
    const float4* hp = (const float4*)(g_hs   + (size_t)v * 16);

    float h[16];
    #pragma unroll
    for (int q = 0; q < 4; q++) {
        float4 a = ap[q], b = hp[q];
        h[4*q+0] = fmaxf(fmaf(dv, a.x + b.x, b1s[4*q+0]), 0.f);
        h[4*q+1] = fmaxf(fmaf(dv, a.y + b.y, b1s[4*q+1]), 0.f);
        h[4*q+2] = fmaxf(fmaf(dv, a.z + b.z, b1s[4*q+2]), 0.f);
        h[4*q+3] = fmaxf(fmaf(dv, a.w + b.w, b1s[4*q+3]), 0.f);
    }

    float o[7] = {0.f, 0.f, 0.f, 0.f, 0.f, 0.f, 0.f};
    #pragma unroll
    for (int k = 0; k < 16; k++) {
        float hk = h[k];
        #pragma unroll
        for (int j = 0; j < 7; j++) o[j] += hk * W2s[k * 7 + j];
    }

    float4* out = (float4*)(g_hs2 + (size_t)v * 8);
    out[0] = make_float4(o[0]*dv, o[1]*dv, o[2]*dv, o[3]*dv);
    out[1] = make_float4(o[4]*dv, o[5]*dv, o[6]*dv, 0.f);
}

// ---- edge scatter, layer 2: acc2[dst] += hs2[src], 2 threads per edge --------
__global__ void k_scatter2(const int* __restrict__ src,
                           const int* __restrict__ dst, int E) {
    int i = blockIdx.x * blockDim.x + threadIdx.x;
    int e = i >> 1;
    if (e >= E) return;
    int q = i & 1;
    size_t s = (size_t)src[e];
    size_t d = (size_t)dst[e];
    float4 a = __ldg((const float4*)(g_hs2 + s * 8) + q);
    float* o = g_acc2 + d * 8 + q * 4;
    atomicAdd(o + 0, a.x);
    atomicAdd(o + 1, a.y);
    atomicAdd(o + 2, a.z);
    if (q == 0) atomicAdd(o + 3, a.w);   // element 7 is padding -> skip when q==1
}

// ---- final: o = dinv*(acc2+hs2) + b2, then log_softmax -----------------------
__global__ void k_final(const float* __restrict__ b2, float* __restrict__ out, int n) {
    int v = blockIdx.x * blockDim.x + threadIdx.x;
    if (v >= n) return;
    float dv = g_dinv[v];
    const float4* ap = (const float4*)(g_acc2 + (size_t)v * 8);
    const float4* hp = (const float4*)(g_hs2  + (size_t)v * 8);
    float4 a0 = ap[0], a1 = ap[1];
    float4 h0 = hp[0], h1 = hp[1];

    float o[7];
    o[0] = fmaf(dv, a0.x + h0.x, __ldg(b2 + 0));
    o[1] = fmaf(dv, a0.y + h0.y, __ldg(b2 + 1));
    o[2] = fmaf(dv, a0.z + h0.z, __ldg(b2 + 2));
    o[3] = fmaf(dv, a0.w + h0.w, __ldg(b2 + 3));
    o[4] = fmaf(dv, a1.x + h1.x, __ldg(b2 + 4));
    o[5] = fmaf(dv, a1.y + h1.y, __ldg(b2 + 5));
    o[6] = fmaf(dv, a1.z + h1.z, __ldg(b2 + 6));

    float m = o[0];
    #pragma unroll
    for (int j = 1; j < 7; j++) m = fmaxf(m, o[j]);
    float s = 0.f;
    #pragma unroll
    for (int j = 0; j < 7; j++) s += expf(o[j] - m);
    float l = logf(s) + m;
    #pragma unroll
    for (int j = 0; j < 7; j++) out[(size_t)v * 7 + j] = o[j] - l;
}

// ---------------------------------------------------------------------------
extern "C" void kernel_launch(void* const* d_in, const int* in_sizes, int n_in,
                              void* d_out, int out_size) {
    const float* x  = (const float*)d_in[0];
    const int*   ei = (const int*)d_in[1];      // int32! (JAX x64 disabled)
    const float* W1 = (const float*)d_in[2];
    const float* b1 = (const float*)d_in[3];
    const float* W2 = (const float*)d_in[4];
    const float* b2 = (const float*)d_in[5];

    int n = in_sizes[0] / 512;     // 100000
    int E = in_sizes[1] / 2;       // 3200000
    const int* src = ei;
    const int* dst = ei + E;

    int nb = (n + 255) / 256;
    int eb = (E + 255) / 256;

    k_init    <<<nb, 256>>>(n);
    k_deg     <<<eb, 256>>>(dst, E);
    k_dinv    <<<nb, 256>>>(n);
    k_gemm1   <<<(n + 31) / 32, 256>>>(x, W1, n);
    k_scatter1<<<(4 * E + 255) / 256, 256>>>(src, dst, E);
    k_layer2  <<<nb, 256>>>(b1, W2, n);
    k_scatter2<<<(2 * E + 255) / 256, 256>>>(src, dst, E);
    k_final   <<<nb, 256>>>(b2, (float*)d_out, n);
}

// round 4
// speedup vs baseline: 1.4011x; 1.4011x over previous
#include <cuda_runtime.h>

// ---------------------------------------------------------------------------
// GCN_13898514169996: 2-layer GCN, N=100000, E=3.2M, 512->16->7.
// gcn(h)[v] = dinv[v] * ( sum_{u->v} h[u]*dinv[u] + h[v]*dinv[v] ) + b
// deg[v] = 1 + indeg(v), dinv = rsqrt(deg). edge_index is int32.
// ---------------------------------------------------------------------------

#define MAXN 100000

__device__ float g_hs  [MAXN * 16];
__device__ float g_acc1[MAXN * 16];
__device__ float g_hs2 [MAXN * 8];
__device__ float g_acc2[MAXN * 8];
__device__ int   g_deg [MAXN];
__device__ float g_dinv[MAXN];

// ---- init: deg=1 (self loop), zero accumulators -----------------------------
__global__ void k_init(int n) {
    int v = blockIdx.x * blockDim.x + threadIdx.x;
    if (v >= n) return;
    g_deg[v] = 1;
    float4 z = make_float4(0.f, 0.f, 0.f, 0.f);
    float4* a1 = (float4*)(g_acc1 + (size_t)v * 16);
    a1[0] = z; a1[1] = z; a1[2] = z; a1[3] = z;
    float4* a2 = (float4*)(g_acc2 + (size_t)v * 8);
    a2[0] = z; a2[1] = z;
}

__global__ void k_deg(const int* __restrict__ dst, int E) {
    int i = blockIdx.x * blockDim.x + threadIdx.x;
    if (i >= E) return;
    atomicAdd(&g_deg[dst[i]], 1);
}

__global__ void k_dinv(int n) {
    int v = blockIdx.x * blockDim.x + threadIdx.x;
    if (v >= n) return;
    g_dinv[v] = rsqrtf((float)g_deg[v]);
}

// ---- GEMM1: hs = (X @ W1) * dinv[row] ---------------------------------------
// 128 threads/block, 256 rows/block. Thread tile: R=8 rows x T=4 cols.
// lane: rg = t>>2 (0..31), c = t&3. Thread rows: rg + 32*i (i=0..7) -> the 8
// row-addresses within a warp (rg=0..7) stride 80B in smem = conflict-free.
// K processed in 32 chunks of 16; X chunk staged in smem (stride 20 floats),
// W chunk (16x16=1KB) staged per chunk.
__global__ void __launch_bounds__(128, 5) k_gemm1(const float* __restrict__ x,
                                                  const float* __restrict__ W1,
                                                  int n) {
    __shared__ float Xs[256 * 20];   // [row][k] stride 20 (pad 4)
    __shared__ float Wsc[16 * 16];   // [k_local][col]

    int t   = threadIdx.x;
    int c   = t & 3;                 // col group: cols 4c..4c+3
    int rg  = t >> 2;                // 0..31
    int row0 = blockIdx.x * 256;

    float acc[8][4];
    #pragma unroll
    for (int i = 0; i < 8; i++)
        #pragma unroll
        for (int j = 0; j < 4; j++) acc[i][j] = 0.f;

    #pragma unroll 1
    for (int ch = 0; ch < 32; ch++) {
        int k0 = ch * 16;
        __syncthreads();
        // W chunk: 16x16 floats; thread loads one float2
        {
            int kl = t >> 3, jj = (t & 7) << 1;
            float2 w = *(const float2*)(W1 + (size_t)(k0 + kl) * 16 + jj);
            *(float2*)(Wsc + kl * 16 + jj) = w;
        }
        // X chunk: 256 rows x 16 k, 8 passes of (32 rows x 4 quarters)
        #pragma unroll
        for (int p = 0; p < 8; p++) {
            int rr = p * 32 + (t >> 2);
            int q  = t & 3;
            int grow = row0 + rr;
            float4 v = make_float4(0.f, 0.f, 0.f, 0.f);
            if (grow < n)
                v = __ldg((const float4*)(x + (size_t)grow * 512 + k0) + q);
            *(float4*)(Xs + rr * 20 + q * 4) = v;
        }
        __syncthreads();

        #pragma unroll
        for (int k4 = 0; k4 < 4; k4++) {
            float4 w0 = *(float4*)(Wsc + (k4 * 4 + 0) * 16 + c * 4);
            float4 w1 = *(float4*)(Wsc + (k4 * 4 + 1) * 16 + c * 4);
            float4 w2 = *(float4*)(Wsc + (k4 * 4 + 2) * 16 + c * 4);
            float4 w3 = *(float4*)(Wsc + (k4 * 4 + 3) * 16 + c * 4);
            #pragma unroll
            for (int i = 0; i < 8; i++) {
                float4 xv = *(float4*)(Xs + (rg + 32 * i) * 20 + k4 * 4);
                acc[i][0] += xv.x * w0.x + xv.y * w1.x + xv.z * w2.x + xv.w * w3.x;
                acc[i][1] += xv.x * w0.y + xv.y * w1.y + xv.z * w2.y + xv.w * w3.y;
                acc[i][2] += xv.x * w0.z + xv.y * w1.z + xv.z * w2.z + xv.w * w3.z;
                acc[i][3] += xv.x * w0.w + xv.y * w1.w + xv.z * w2.w + xv.w * w3.w;
            }
        }
    }

    // epilogue: scale by dinv[row], store float4 (coalesced across warp)
    #pragma unroll
    for (int i = 0; i < 8; i++) {
        int row = row0 + rg + 32 * i;
        if (row >= n) continue;
        float dv = g_dinv[row];
        float4 o = make_float4(acc[i][0] * dv, acc[i][1] * dv,
                               acc[i][2] * dv, acc[i][3] * dv);
        *(float4*)(g_hs + (size_t)row * 16 + c * 4) = o;
    }
}

// ---- edge scatter, layer 1: acc1[dst] += hs[src] (16 floats, 4x RED.128) ----
__global__ void k_scatter1(const int* __restrict__ src,
                           const int* __restrict__ dst, int E) {
    int e = blockIdx.x * blockDim.x + threadIdx.x;
    if (e >= E) return;
    size_t s = (size_t)src[e];
    size_t d = (size_t)dst[e];
    const float4* hp = (const float4*)(g_hs + s * 16);
    float4 a0 = __ldg(hp + 0), a1 = __ldg(hp + 1);
    float4 a2 = __ldg(hp + 2), a3 = __ldg(hp + 3);
    float* o = g_acc1 + d * 16;
    asm volatile("red.global.add.v4.f32 [%0], {%1,%2,%3,%4};"
                 :: "l"(o +  0), "f"(a0.x), "f"(a0.y), "f"(a0.z), "f"(a0.w) : "memory");
    asm volatile("red.global.add.v4.f32 [%0], {%1,%2,%3,%4};"
                 :: "l"(o +  4), "f"(a1.x), "f"(a1.y), "f"(a1.z), "f"(a1.w) : "memory");
    asm volatile("red.global.add.v4.f32 [%0], {%1,%2,%3,%4};"
                 :: "l"(o +  8), "f"(a2.x), "f"(a2.y), "f"(a2.z), "f"(a2.w) : "memory");
    asm volatile("red.global.add.v4.f32 [%0], {%1,%2,%3,%4};"
                 :: "l"(o + 12), "f"(a3.x), "f"(a3.y), "f"(a3.z), "f"(a3.w) : "memory");
}

// ---- layer-1 epilogue + layer-2 node GEMM ------------------------------------
__global__ void __launch_bounds__(256) k_layer2(const float* __restrict__ b1,
                                                const float* __restrict__ W2,
                                                int n) {
    __shared__ float W2s[112];
    __shared__ float b1s[16];
    int t = threadIdx.x;
    if (t < 112) W2s[t] = W2[t];
    if (t < 16)  b1s[t] = b1[t];
    __syncthreads();

    int v = blockIdx.x * 256 + t;
    if (v >= n) return;
    float dv = g_dinv[v];
    const float4* ap = (const float4*)(g_acc1 + (size_t)v * 16);
    const float4* hp = (const float4*)(g_hs   + (size_t)v * 16);

    float h[16];
    #pragma unroll
    for (int q = 0; q < 4; q++) {
        float4 a = ap[q], b = hp[q];
        h[4*q+0] = fmaxf(fmaf(dv, a.x + b.x, b1s[4*q+0]), 0.f);
        h[4*q+1] = fmaxf(fmaf(dv, a.y + b.y, b1s[4*q+1]), 0.f);
        h[4*q+2] = fmaxf(fmaf(dv, a.z + b.z, b1s[4*q+2]), 0.f);
        h[4*q+3] = fmaxf(fmaf(dv, a.w + b.w, b1s[4*q+3]), 0.f);
    }

    float o[7] = {0.f, 0.f, 0.f, 0.f, 0.f, 0.f, 0.f};
    #pragma unroll
    for (int k = 0; k < 16; k++) {
        float hk = h[k];
        #pragma unroll
        for (int j = 0; j < 7; j++) o[j] += hk * W2s[k * 7 + j];
    }

    float4* out = (float4*)(g_hs2 + (size_t)v * 8);
    out[0] = make_float4(o[0]*dv, o[1]*dv, o[2]*dv, o[3]*dv);
    out[1] = make_float4(o[4]*dv, o[5]*dv, o[6]*dv, 0.f);
}

// ---- edge scatter, layer 2: acc2[dst] += hs2[src] (8 floats, 2x RED.128) ----
__global__ void k_scatter2(const int* __restrict__ src,
                           const int* __restrict__ dst, int E) {
    int e = blockIdx.x * blockDim.x + threadIdx.x;
    if (e >= E) return;
    size_t s = (size_t)src[e];
    size_t d = (size_t)dst[e];
    const float4* hp = (const float4*)(g_hs2 + s * 8);
    float4 a0 = __ldg(hp + 0), a1 = __ldg(hp + 1);
    float* o = g_acc2 + d * 8;
    asm volatile("red.global.add.v4.f32 [%0], {%1,%2,%3,%4};"
                 :: "l"(o + 0), "f"(a0.x), "f"(a0.y), "f"(a0.z), "f"(a0.w) : "memory");
    asm volatile("red.global.add.v4.f32 [%0], {%1,%2,%3,%4};"
                 :: "l"(o + 4), "f"(a1.x), "f"(a1.y), "f"(a1.z), "f"(a1.w) : "memory");
}

// ---- final: o = dinv*(acc2+hs2) + b2, then log_softmax -----------------------
__global__ void k_final(const float* __restrict__ b2, float* __restrict__ out, int n) {
    int v = blockIdx.x * blockDim.x + threadIdx.x;
    if (v >= n) return;
    float dv = g_dinv[v];
    const float4* ap = (const float4*)(g_acc2 + (size_t)v * 8);
    const float4* hp = (const float4*)(g_hs2  + (size_t)v * 8);
    float4 a0 = ap[0], a1 = ap[1];
    float4 h0 = hp[0], h1 = hp[1];

    float o[7];
    o[0] = fmaf(dv, a0.x + h0.x, __ldg(b2 + 0));
    o[1] = fmaf(dv, a0.y + h0.y, __ldg(b2 + 1));
    o[2] = fmaf(dv, a0.z + h0.z, __ldg(b2 + 2));
    o[3] = fmaf(dv, a0.w + h0.w, __ldg(b2 + 3));
    o[4] = fmaf(dv, a1.x + h1.x, __ldg(b2 + 4));
    o[5] = fmaf(dv, a1.y + h1.y, __ldg(b2 + 5));
    o[6] = fmaf(dv, a1.z + h1.z, __ldg(b2 + 6));

    float m = o[0];
    #pragma unroll
    for (int j = 1; j < 7; j++) m = fmaxf(m, o[j]);
    float s = 0.f;
    #pragma unroll
    for (int j = 0; j < 7; j++) s += expf(o[j] - m);
    float l = logf(s) + m;
    #pragma unroll
    for (int j = 0; j < 7; j++) out[(size_t)v * 7 + j] = o[j] - l;
}

// ---------------------------------------------------------------------------
extern "C" void kernel_launch(void* const* d_in, const int* in_sizes, int n_in,
                              void* d_out, int out_size) {
    const float* x  = (const float*)d_in[0];
    const int*   ei = (const int*)d_in[1];      // int32 (JAX x64 disabled)
    const float* W1 = (const float*)d_in[2];
    const float* b1 = (const float*)d_in[3];
    const float* W2 = (const float*)d_in[4];
    const float* b2 = (const float*)d_in[5];

    int n = in_sizes[0] / 512;     // 100000
    int E = in_sizes[1] / 2;       // 3200000
    const int* src = ei;
    const int* dst = ei + E;

    int nb = (n + 255) / 256;
    int eb = (E + 255) / 256;

    k_init    <<<nb, 256>>>(n);
    k_deg     <<<eb, 256>>>(dst, E);
    k_dinv    <<<nb, 256>>>(n);
    k_gemm1   <<<(n + 255) / 256, 128>>>(x, W1, n);
    k_scatter1<<<eb, 256>>>(src, dst, E);
    k_layer2  <<<nb, 256>>>(b1, W2, n);
    k_scatter2<<<eb, 256>>>(src, dst, E);
    k_final   <<<nb, 256>>>(b2, (float*)d_out, n);
}